// round 2
// baseline (speedup 1.0000x reference)
#include <cuda_runtime.h>
#include <math.h>

#define G 4
#define NNODE 1024
#define FDIM 256
#define HDIM 256
#define BATCH 32
#define LAYERS 4

// Scratch (device globals; no allocation allowed)
__device__ float g_h0[G * NNODE * HDIM];   // residual / input activations
__device__ float g_t [G * NNODE * HDIM];   // A @ x result
__device__ float g_xa[G * NNODE * HDIM];   // ping
__device__ float g_xb[G * NNODE * HDIM];   // pong

// ---------------------------------------------------------------------------
// Generic batched GEMM: C[z] = act(A[z] @ B[z] + bias), row-major.
// BM=BN=64, BK=16, 256 threads, 4x4 per-thread microtile.
// All problem dims here are multiples of 64/16 -> no bounds checks.
// ACT: 0 = none, 1 = relu, 2 = tanh
// ---------------------------------------------------------------------------
template <int ACT>
__global__ void gemm_kernel(const float* __restrict__ A,
                            const float* __restrict__ Bm,
                            const float* __restrict__ bias,
                            float* __restrict__ C,
                            int M, int Nd, int K,
                            long sA, long sB, long sC) {
    A  += (long)blockIdx.z * sA;
    Bm += (long)blockIdx.z * sB;
    C  += (long)blockIdx.z * sC;

    __shared__ float As[16][64];   // [k][m]
    __shared__ float Bs[16][64];   // [k][n]

    const int tid = threadIdx.x;
    const int tx = tid & 15;       // 0..15 -> n
    const int ty = tid >> 4;       // 0..15 -> m
    const int bm = blockIdx.y * 64;
    const int bn = blockIdx.x * 64;

    // global->smem load mapping (one float4 per thread per tile)
    const int am  = tid >> 2;          // 0..63  (row within A tile)
    const int ak  = (tid & 3) * 4;     // 0,4,8,12 (k within A tile)
    const int bk  = tid >> 4;          // 0..15  (k within B tile)
    const int bn4 = (tid & 15) * 4;    // 0..60  (n within B tile)

    float acc[4][4] = {};

    for (int k0 = 0; k0 < K; k0 += 16) {
        float4 av = *(const float4*)(A  + (size_t)(bm + am) * K  + k0 + ak);
        float4 bv = *(const float4*)(Bm + (size_t)(k0 + bk) * Nd + bn + bn4);
        As[ak + 0][am] = av.x;
        As[ak + 1][am] = av.y;
        As[ak + 2][am] = av.z;
        As[ak + 3][am] = av.w;
        *(float4*)&Bs[bk][bn4] = bv;
        __syncthreads();

        #pragma unroll
        for (int k = 0; k < 16; k++) {
            float4 a = *(const float4*)&As[k][ty * 4];
            float4 b = *(const float4*)&Bs[k][tx * 4];
            acc[0][0] += a.x * b.x; acc[0][1] += a.x * b.y; acc[0][2] += a.x * b.z; acc[0][3] += a.x * b.w;
            acc[1][0] += a.y * b.x; acc[1][1] += a.y * b.y; acc[1][2] += a.y * b.z; acc[1][3] += a.y * b.w;
            acc[2][0] += a.z * b.x; acc[2][1] += a.z * b.y; acc[2][2] += a.z * b.z; acc[2][3] += a.z * b.w;
            acc[3][0] += a.w * b.x; acc[3][1] += a.w * b.y; acc[3][2] += a.w * b.z; acc[3][3] += a.w * b.w;
        }
        __syncthreads();
    }

    #pragma unroll
    for (int i = 0; i < 4; i++) {
        const int row = bm + ty * 4 + i;
        #pragma unroll
        for (int j = 0; j < 4; j++) {
            const int col = bn + tx * 4 + j;
            float v = acc[i][j];
            if (bias) v += bias[col];
            if (ACT == 1) v = fmaxf(v, 0.0f);
            if (ACT == 2) v = tanhf(v);
            C[(size_t)row * Nd + col] = v;
        }
    }
}

// ---------------------------------------------------------------------------
// out[b,h] = sum_n mask[b,n]*(x[g,n,h] + h0[g,n,h]) / max(sum_n mask, 1)
// one block per b, 256 threads (one per h). mask is int32 (bool -> int32).
// ---------------------------------------------------------------------------
__global__ void reduce_kernel(const float* __restrict__ x,
                              const float* __restrict__ r,
                              const int* __restrict__ gidx,
                              const int* __restrict__ mask,
                              float* __restrict__ out) {
    const int b = blockIdx.x;
    const int h = threadIdx.x;
    const int g = gidx[b];
    const float* xb = x + (size_t)g * NNODE * HDIM;
    const float* rb = r + (size_t)g * NNODE * HDIM;
    const int* mb = mask + b * NNODE;

    float acc = 0.0f;
    float cnt = 0.0f;
    #pragma unroll 8
    for (int n = 0; n < NNODE; n++) {
        float m = (mb[n] != 0) ? 1.0f : 0.0f;
        cnt += m;
        acc += m * (xb[(size_t)n * HDIM + h] + rb[(size_t)n * HDIM + h]);
    }
    out[b * HDIM + h] = acc / fmaxf(cnt, 1.0f);
}

extern "C" void kernel_launch(void* const* d_in, const int* in_sizes, int n_in,
                              void* d_out, int out_size) {
    const float* batch_xs = (const float*)d_in[0];           // [G,N,F]
    const float* batch_as = (const float*)d_in[1];           // [G,N,N]
    const float* w_in     = (const float*)d_in[2];           // [F,H]
    const float* b_in     = (const float*)d_in[3];           // [H]
    const float* gcn_w    = (const float*)d_in[4];           // [L,H,H]
    const float* gcn_b    = (const float*)d_in[5];           // [L,H]
    const int*   gidx     = (const int*)d_in[6];             // [B]
    const int*   cp_mask  = (const int*)d_in[7];             // [B,N] bool->int32
    float* out = (float*)d_out;                              // [B,H]

    float *h0, *t, *xa, *xb;
    cudaGetSymbolAddress((void**)&h0, g_h0);
    cudaGetSymbolAddress((void**)&t,  g_t);
    cudaGetSymbolAddress((void**)&xa, g_xa);
    cudaGetSymbolAddress((void**)&xb, g_xb);

    const int MG = G * NNODE;  // 4096

    // Input dense layer: h0 = relu(Xg @ w_in + b_in), single GEMM M=4096
    gemm_kernel<1><<<dim3(HDIM / 64, MG / 64, 1), 256>>>(
        batch_xs, w_in, b_in, h0, MG, HDIM, FDIM, 0, 0, 0);

    const float* cur = h0;
    float* bufs[2] = {xa, xb};
    for (int i = 0; i < LAYERS; i++) {
        // t[g] = A[g] @ cur[g]  (batched over z = g)
        gemm_kernel<0><<<dim3(HDIM / 64, NNODE / 64, G), 256>>>(
            batch_as, cur, nullptr, t,
            NNODE, HDIM, NNODE,
            (long)NNODE * NNODE, (long)NNODE * HDIM, (long)NNODE * HDIM);
        // next = act(t @ W_i + b_i), single GEMM M=4096
        float* nxt = bufs[i & 1];
        if (i < LAYERS - 1) {
            gemm_kernel<1><<<dim3(HDIM / 64, MG / 64, 1), 256>>>(
                t, gcn_w + (size_t)i * HDIM * HDIM, gcn_b + i * HDIM, nxt,
                MG, HDIM, HDIM, 0, 0, 0);
        } else {
            gemm_kernel<2><<<dim3(HDIM / 64, MG / 64, 1), 256>>>(
                t, gcn_w + (size_t)i * HDIM * HDIM, gcn_b + i * HDIM, nxt,
                MG, HDIM, HDIM, 0, 0, 0);
        }
        cur = nxt;
    }

    // masked mean with residual fold-in
    reduce_kernel<<<BATCH, HDIM>>>(cur, h0, gidx, cp_mask, out);
}

// round 4
// speedup vs baseline: 2.2040x; 2.2040x over previous
#include <cuda_runtime.h>
#include <math.h>
#include <stdint.h>

#define G 4
#define NNODE 1024
#define FDIM 256
#define HDIM 256
#define BATCH 32
#define LAYERS 4

// ---------------- scratch (device globals; no allocation allowed) -----------
__device__ float g_ar[G * NNODE * NNODE];            // tf32-rounded adjacency
__device__ float g_xr[G * NNODE * FDIM];             // tf32-rounded input feats
__device__ float g_wr[(1 + LAYERS) * HDIM * HDIM];   // tf32-rounded weights
__device__ float g_h0[G * NNODE * HDIM];             // residual / layer-0 input (tf32-rounded)
__device__ float g_t [G * NNODE * HDIM];             // A @ x
__device__ float g_x [G * NNODE * HDIM];             // hidden activations
__device__ float g_xl[G * NNODE * HDIM];             // final layer output (full fp32)

// ---------------- tiling ----------------------------------------------------
#define BM 64
#define BN 128
#define BK 32
#define NSTAGE 3
#define ASTR 36                       // smem row stride (floats) for A tile [64][36]
#define BSTR 136                      // smem row stride (floats) for B tile [32][136]
#define A_STG (BM * ASTR)             // 2304 floats
#define B_STG (BK * BSTR)             // 4352 floats
#define SM_FLOATS (BN + NSTAGE * (A_STG + B_STG))
#define SMEM_BYTES (SM_FLOATS * 4)    // ~80.4 KB

__device__ __forceinline__ uint32_t smem_u32(const void* p) {
    uint32_t a;
    asm("{ .reg .u64 t; cvta.to.shared.u64 t, %1; cvt.u32.u64 %0, t; }" : "=r"(a) : "l"(p));
    return a;
}
__device__ __forceinline__ void cpa16(uint32_t dst, const void* src) {
    asm volatile("cp.async.cg.shared.global [%0], [%1], 16;" :: "r"(dst), "l"(src));
}
#define CP_COMMIT() asm volatile("cp.async.commit_group;" ::: "memory")
#define CP_WAIT1()  asm volatile("cp.async.wait_group 1;" ::: "memory")

__device__ __forceinline__ float rna_tf32(float x) {
    uint32_t u;
    asm("cvt.rna.tf32.f32 %0, %1;" : "=r"(u) : "f"(x));
    return __uint_as_float(u);
}

__device__ __forceinline__ void mma_tf32(float* d, const uint32_t* a,
                                         uint32_t b0, uint32_t b1) {
    asm volatile(
        "mma.sync.aligned.m16n8k8.row.col.f32.tf32.tf32.f32 "
        "{%0,%1,%2,%3}, {%4,%5,%6,%7}, {%8,%9}, {%0,%1,%2,%3};"
        : "+f"(d[0]), "+f"(d[1]), "+f"(d[2]), "+f"(d[3])
        : "r"(a[0]), "r"(a[1]), "r"(a[2]), "r"(a[3]), "r"(b0), "r"(b1));
}

// ---------------- tf32 mma.sync GEMM ----------------------------------------
// C = act(A @ B + bias); A [M,K] row-major, B [K,N=256] row-major, C row-major.
// ACT: 0 none, 1 relu, 2 tanh. RND: round outputs to tf32 (feeds next GEMM).
template <int ACT, bool RND>
__global__ void __launch_bounds__(256, 2)
tc_gemm(const float* __restrict__ A, const float* __restrict__ B,
        const float* __restrict__ bias, float* __restrict__ C,
        int K, long sAz, long sBz, long sCz) {
    extern __shared__ float sm[];
    float* sbias = sm;                         // [BN]
    float* sA = sm + BN;                       // [NSTAGE][A_STG]
    float* sB = sA + NSTAGE * A_STG;           // [NSTAGE][B_STG]
    const uint32_t uA = smem_u32(sA);
    const uint32_t uB = smem_u32(sB);

    const int tid = threadIdx.x;
    const int wid = tid >> 5, lane = tid & 31;
    const int wm = wid >> 2, wn = wid & 3;     // warp grid 2 x 4
    const int gid = lane >> 2, tig = lane & 3;
    const int bx = blockIdx.x, by = blockIdx.y, bz = blockIdx.z;

    A += (long)bz * sAz + (long)(by * BM) * K;
    B += (long)bz * sBz + (long)bx * BN;
    C += (long)bz * sCz;

    if (bias && tid < BN) sbias[tid] = bias[bx * BN + tid];

    const int NC = K / BK;

    // global -> smem stage loader (cp.async, 16B, raw fp32 already tf32-rounded)
    auto load_stage = [&](int c, int s) {
        const float* Ag = A + c * BK;
        const float* Bg = B + (long)(c * BK) * HDIM;
        uint32_t aBase = uA + s * A_STG * 4;
        uint32_t bBase = uB + s * B_STG * 4;
        #pragma unroll
        for (int i = 0; i < 2; i++) {             // A: 64 rows x 8 float4
            int idx = tid + i * 256;
            int r = idx >> 3, q = idx & 7;
            cpa16(aBase + (r * ASTR + q * 4) * 4, Ag + (long)r * K + q * 4);
        }
        #pragma unroll
        for (int i = 0; i < 4; i++) {             // B: 32 rows x 32 float4
            int idx = tid + i * 256;
            int r = idx >> 5, q = idx & 31;
            cpa16(bBase + (r * BSTR + q * 4) * 4, Bg + (long)r * HDIM + q * 4);
        }
    };

    float d[2][4][4] = {};

    load_stage(0, 0); CP_COMMIT();
    load_stage(1, 1); CP_COMMIT();

    for (int c = 0; c < NC; c++) {
        CP_WAIT1();
        __syncthreads();
        if (c + 2 < NC) {
            int s = (c + 2) % NSTAGE;
            load_stage(c + 2, s);
        }
        CP_COMMIT();

        const int s = c % NSTAGE;
        const float* as = sA + s * A_STG;
        const float* bs = sB + s * B_STG;
        #pragma unroll
        for (int ks = 0; ks < 4; ks++) {
            const int k0 = ks * 8 + tig;
            uint32_t a[2][4];
            #pragma unroll
            for (int mt = 0; mt < 2; mt++) {
                const int m0 = wm * 32 + mt * 16 + gid;
                a[mt][0] = __float_as_uint(as[m0 * ASTR + k0]);
                a[mt][1] = __float_as_uint(as[(m0 + 8) * ASTR + k0]);
                a[mt][2] = __float_as_uint(as[m0 * ASTR + k0 + 4]);
                a[mt][3] = __float_as_uint(as[(m0 + 8) * ASTR + k0 + 4]);
            }
            #pragma unroll
            for (int nt = 0; nt < 4; nt++) {
                const int n0 = wn * 32 + nt * 8 + gid;
                uint32_t b0 = __float_as_uint(bs[k0 * BSTR + n0]);
                uint32_t b1 = __float_as_uint(bs[(k0 + 4) * BSTR + n0]);
                mma_tf32(d[0][nt], a[0], b0, b1);
                mma_tf32(d[1][nt], a[1], b0, b1);
            }
        }
        __syncthreads();
    }

    // epilogue: bias + act (+ tf32 rounding), float2 stores
    #pragma unroll
    for (int mt = 0; mt < 2; mt++) {
        #pragma unroll
        for (int half = 0; half < 2; half++) {
            const long row = (long)by * BM + wm * 32 + mt * 16 + gid + half * 8;
            #pragma unroll
            for (int nt = 0; nt < 4; nt++) {
                const int cl = wn * 32 + nt * 8 + 2 * tig;   // col within BN tile
                float v0 = d[mt][nt][half * 2 + 0];
                float v1 = d[mt][nt][half * 2 + 1];
                if (bias) { v0 += sbias[cl]; v1 += sbias[cl + 1]; }
                if (ACT == 1) { v0 = fmaxf(v0, 0.0f); v1 = fmaxf(v1, 0.0f); }
                if (ACT == 2) { v0 = tanhf(v0); v1 = tanhf(v1); }
                if (RND) { v0 = rna_tf32(v0); v1 = rna_tf32(v1); }
                *(float2*)(C + row * HDIM + bx * BN + cl) = make_float2(v0, v1);
            }
        }
    }
}

// ---------------- tf32 round-copy prep ---------------------------------------
__global__ void round_copy(const float4* __restrict__ src, float4* __restrict__ dst, int n4) {
    int i = blockIdx.x * blockDim.x + threadIdx.x;
    if (i < n4) {
        float4 v = src[i];
        v.x = rna_tf32(v.x); v.y = rna_tf32(v.y);
        v.z = rna_tf32(v.z); v.w = rna_tf32(v.w);
        dst[i] = v;
    }
}

// ---------------- masked mean + residual ------------------------------------
__global__ void reduce_kernel(const float* __restrict__ x,
                              const float* __restrict__ r,
                              const int* __restrict__ gidx,
                              const int* __restrict__ mask,
                              float* __restrict__ out) {
    const int b = blockIdx.x;
    const int h = threadIdx.x;
    const int g = gidx[b];
    const float* xb = x + (size_t)g * NNODE * HDIM;
    const float* rb = r + (size_t)g * NNODE * HDIM;
    const int* mb = mask + b * NNODE;

    float acc = 0.0f, cnt = 0.0f;
    #pragma unroll 8
    for (int n = 0; n < NNODE; n++) {
        float m = (mb[n] != 0) ? 1.0f : 0.0f;
        cnt += m;
        acc += m * (xb[(size_t)n * HDIM + h] + rb[(size_t)n * HDIM + h]);
    }
    out[b * HDIM + h] = acc / fmaxf(cnt, 1.0f);
}

// ---------------- launch -----------------------------------------------------
extern "C" void kernel_launch(void* const* d_in, const int* in_sizes, int n_in,
                              void* d_out, int out_size) {
    const float* batch_xs = (const float*)d_in[0];
    const float* batch_as = (const float*)d_in[1];
    const float* w_in     = (const float*)d_in[2];
    const float* b_in     = (const float*)d_in[3];
    const float* gcn_w    = (const float*)d_in[4];
    const float* gcn_b    = (const float*)d_in[5];
    const int*   gidx     = (const int*)d_in[6];
    const int*   cp_mask  = (const int*)d_in[7];
    float* out = (float*)d_out;

    float *ar, *xr, *wr, *h0, *t, *x, *xl;
    cudaGetSymbolAddress((void**)&ar, g_ar);
    cudaGetSymbolAddress((void**)&xr, g_xr);
    cudaGetSymbolAddress((void**)&wr, g_wr);
    cudaGetSymbolAddress((void**)&h0, g_h0);
    cudaGetSymbolAddress((void**)&t,  g_t);
    cudaGetSymbolAddress((void**)&x,  g_x);
    cudaGetSymbolAddress((void**)&xl, g_xl);

    cudaFuncSetAttribute(tc_gemm<0, true >, cudaFuncAttributeMaxDynamicSharedMemorySize, SMEM_BYTES);
    cudaFuncSetAttribute(tc_gemm<1, true >, cudaFuncAttributeMaxDynamicSharedMemorySize, SMEM_BYTES);
    cudaFuncSetAttribute(tc_gemm<2, false>, cudaFuncAttributeMaxDynamicSharedMemorySize, SMEM_BYTES);

    // prep: round inputs/weights to tf32 precision (RNA)
    {
        int n4;
        n4 = G * NNODE * NNODE / 4;
        round_copy<<<(n4 + 255) / 256, 256>>>((const float4*)batch_as, (float4*)ar, n4);
        n4 = G * NNODE * FDIM / 4;
        round_copy<<<(n4 + 255) / 256, 256>>>((const float4*)batch_xs, (float4*)xr, n4);
        n4 = FDIM * HDIM / 4;
        round_copy<<<(n4 + 255) / 256, 256>>>((const float4*)w_in, (float4*)wr, n4);
        n4 = LAYERS * HDIM * HDIM / 4;
        round_copy<<<(n4 + 255) / 256, 256>>>((const float4*)gcn_w,
                                              (float4*)(wr + HDIM * HDIM), n4);
    }

    const int MG = G * NNODE;  // 4096

    // input dense: h0 = relu(X @ w_in + b), rounded for reuse as layer-0 input
    tc_gemm<1, true><<<dim3(HDIM / BN, MG / BM, 1), 256, SMEM_BYTES>>>(
        xr, wr, b_in, h0, FDIM, 0, 0, 0);

    const float* cur = h0;
    for (int i = 0; i < LAYERS; i++) {
        // t[g] = A[g] @ x[g]
        tc_gemm<0, true><<<dim3(HDIM / BN, NNODE / BM, G), 256, SMEM_BYTES>>>(
            ar, cur, nullptr, t, NNODE,
            (long)NNODE * NNODE, (long)NNODE * HDIM, (long)NNODE * HDIM);
        if (i < LAYERS - 1) {
            tc_gemm<1, true><<<dim3(HDIM / BN, MG / BM, 1), 256, SMEM_BYTES>>>(
                t, wr + (size_t)(1 + i) * HDIM * HDIM, gcn_b + i * HDIM, x,
                HDIM, 0, 0, 0);
            cur = x;
        } else {
            tc_gemm<2, false><<<dim3(HDIM / BN, MG / BM, 1), 256, SMEM_BYTES>>>(
                t, wr + (size_t)LAYERS * HDIM * HDIM, gcn_b + (LAYERS - 1) * HDIM, xl,
                HDIM, 0, 0, 0);
        }
    }

    reduce_kernel<<<BATCH, HDIM>>>(xl, h0, gidx, cp_mask, out);
}

// round 5
// speedup vs baseline: 2.9000x; 1.3158x over previous
#include <cuda_runtime.h>
#include <cuda_fp16.h>
#include <math.h>
#include <stdint.h>

#define G 4
#define NNODE 1024
#define FDIM 256
#define HDIM 256
#define BATCH 32
#define LAYERS 4

// ---------------- scratch (device globals; no allocation allowed) -----------
__device__ __half g_ah [G * NNODE * NNODE];          // adjacency, half, x1024
__device__ __half g_xin[G * NNODE * FDIM];           // input feats, half
__device__ __half g_wh [(1 + LAYERS) * HDIM * HDIM]; // weights, half
__device__ __half g_h0h[G * NNODE * HDIM];           // h0 as half (GEMM input)
__device__ __half g_th [G * NNODE * HDIM];           // A @ x (half)
__device__ __half g_xh [G * NNODE * HDIM];           // hidden activations (half)
__device__ float  g_h0f[G * NNODE * HDIM];           // h0 fp32 (residual)
__device__ float  g_xl [G * NNODE * HDIM];           // final output fp32

// ---------------- tiling ----------------------------------------------------
#define BM 64
#define BN 128
#define BK 64
#define NSTAGE 3
#define ASTR_H 72                         // A smem row stride in halves (144 B)
#define BSTR_H 136                        // B smem row stride in halves (272 B)
#define A_STG_B (BM * ASTR_H * 2)         // 9216 B
#define B_STG_B (BK * BSTR_H * 2)         // 17408 B
#define SM_BIAS_B 512
#define SMEM_BYTES (SM_BIAS_B + NSTAGE * (A_STG_B + B_STG_B))   // 80384 B

__device__ __forceinline__ uint32_t smem_u32(const void* p) {
    uint32_t a;
    asm("{ .reg .u64 t; cvta.to.shared.u64 t, %1; cvt.u32.u64 %0, t; }" : "=r"(a) : "l"(p));
    return a;
}
__device__ __forceinline__ void cpa16(uint32_t dst, const void* src) {
    asm volatile("cp.async.cg.shared.global [%0], [%1], 16;" :: "r"(dst), "l"(src));
}
#define CP_COMMIT() asm volatile("cp.async.commit_group;" ::: "memory")
#define CP_WAIT1()  asm volatile("cp.async.wait_group 1;" ::: "memory")

__device__ __forceinline__ void ldsm_x4(uint32_t* r, uint32_t addr) {
    asm volatile("ldmatrix.sync.aligned.m8n8.x4.shared.b16 {%0,%1,%2,%3}, [%4];"
        : "=r"(r[0]), "=r"(r[1]), "=r"(r[2]), "=r"(r[3]) : "r"(addr));
}
__device__ __forceinline__ void ldsm_x4_t(uint32_t* r, uint32_t addr) {
    asm volatile("ldmatrix.sync.aligned.m8n8.x4.trans.shared.b16 {%0,%1,%2,%3}, [%4];"
        : "=r"(r[0]), "=r"(r[1]), "=r"(r[2]), "=r"(r[3]) : "r"(addr));
}
__device__ __forceinline__ void mma_f16(float* d, const uint32_t* a, uint32_t b0, uint32_t b1) {
    asm volatile(
        "mma.sync.aligned.m16n8k16.row.col.f32.f16.f16.f32 "
        "{%0,%1,%2,%3}, {%4,%5,%6,%7}, {%8,%9}, {%0,%1,%2,%3};"
        : "+f"(d[0]), "+f"(d[1]), "+f"(d[2]), "+f"(d[3])
        : "r"(a[0]), "r"(a[1]), "r"(a[2]), "r"(a[3]), "r"(b0), "r"(b1));
}

// ---------------- fp16 mma.sync GEMM -----------------------------------------
// C = act(oscale * (A @ B) + bias)
// A [M,K] half row-major; B [K,256] half row-major; outputs row-major [.,256].
// ACT: 0 none, 1 relu, 2 tanh. MODE: 0 half out, 1 half+fp32 out, 2 fp32 out.
template <int ACT, int MODE>
__global__ void __launch_bounds__(256)
tc_gemm(const __half* __restrict__ A, const __half* __restrict__ B,
        const float* __restrict__ bias,
        __half* __restrict__ Ch, float* __restrict__ Cf,
        int K, long sAz, long sBz, long sCz, float oscale) {
    extern __shared__ char smraw[];
    float* sbias = (float*)smraw;                       // [BN]
    char* sA = smraw + SM_BIAS_B;                       // NSTAGE x A_STG_B
    char* sB = sA + NSTAGE * A_STG_B;                   // NSTAGE x B_STG_B
    const uint32_t uA = smem_u32(sA);
    const uint32_t uB = smem_u32(sB);

    const int tid = threadIdx.x;
    const int wid = tid >> 5, lane = tid & 31;
    const int wm = wid >> 2, wn = wid & 3;              // warps 2 (M) x 4 (N)
    const int gid = lane >> 2, tig = lane & 3;
    const int bx = blockIdx.x, by = blockIdx.y, bz = blockIdx.z;

    A += (long)bz * sAz + (long)(by * BM) * K;
    B += (long)bz * sBz + (long)bx * BN;

    if (bias && tid < BN) sbias[tid] = bias[bx * BN + tid];

    const int NC = K / BK;

    auto load_stage = [&](int c, int s) {
        const __half* Ag = A + c * BK;
        const __half* Bg = B + (long)(c * BK) * HDIM;
        uint32_t aBase = uA + s * A_STG_B;
        uint32_t bBase = uB + s * B_STG_B;
        #pragma unroll
        for (int i = 0; i < 2; i++) {                   // A: 64 rows x 8 x 16B
            int idx = tid + i * 256;
            int r = idx >> 3, q = idx & 7;
            cpa16(aBase + r * (ASTR_H * 2) + q * 16, Ag + (long)r * K + q * 8);
        }
        #pragma unroll
        for (int i = 0; i < 4; i++) {                   // B: 64 rows x 16 x 16B
            int idx = tid + i * 256;
            int r = idx >> 4, q = idx & 15;
            cpa16(bBase + r * (BSTR_H * 2) + q * 16, Bg + (long)r * HDIM + q * 8);
        }
    };

    // ldmatrix lane addresses (byte offsets inside a stage)
    const int l15 = lane & 15, l4 = lane >> 4;
    // A (non-trans): row = wm*32 + mt*16 + (lane&15); kblk16B = lane>>4
    const uint32_t aLane = (uint32_t)((wm * 32 + l15) * (ASTR_H * 2) + l4 * 16);
    // B (trans): row(k) = kstep*16 + (lane&15); col = wn*32 + pair*16 + (lane>>4)*8
    const uint32_t bLane = (uint32_t)(l15 * (BSTR_H * 2) + (wn * 32 + l4 * 8) * 2);

    float d[2][4][4] = {};

    load_stage(0, 0); CP_COMMIT();
    load_stage(1, 1); CP_COMMIT();

    for (int c = 0; c < NC; c++) {
        CP_WAIT1();
        __syncthreads();
        if (c + 2 < NC) load_stage(c + 2, (c + 2) % NSTAGE);
        CP_COMMIT();

        const int s = c % NSTAGE;
        const uint32_t aS = uA + s * A_STG_B + aLane;
        const uint32_t bS = uB + s * B_STG_B + bLane;

        #pragma unroll
        for (int ks = 0; ks < 4; ks++) {                // 4 x k16 per BK=64
            uint32_t a0[4], a1[4], bp0[4], bp1[4];
            ldsm_x4(a0, aS + ks * 32);                              // m 0..15
            ldsm_x4(a1, aS + ks * 32 + 16 * (ASTR_H * 2));          // m 16..31
            ldsm_x4_t(bp0, bS + ks * 16 * (BSTR_H * 2));            // n 0..15
            ldsm_x4_t(bp1, bS + ks * 16 * (BSTR_H * 2) + 32);       // n 16..31
            // bp[0],bp[1] -> n-frag (first 8 cols); bp[2],bp[3] -> next 8
            mma_f16(d[0][0], a0, bp0[0], bp0[1]);
            mma_f16(d[1][0], a1, bp0[0], bp0[1]);
            mma_f16(d[0][1], a0, bp0[2], bp0[3]);
            mma_f16(d[1][1], a1, bp0[2], bp0[3]);
            mma_f16(d[0][2], a0, bp1[0], bp1[1]);
            mma_f16(d[1][2], a1, bp1[0], bp1[1]);
            mma_f16(d[0][3], a0, bp1[2], bp1[3]);
            mma_f16(d[1][3], a1, bp1[2], bp1[3]);
        }
    }

    // epilogue
    #pragma unroll
    for (int mt = 0; mt < 2; mt++) {
        #pragma unroll
        for (int hf = 0; hf < 2; hf++) {
            const long row = (long)by * BM + wm * 32 + mt * 16 + gid + hf * 8;
            const long rc = (long)bz * sCz + row * HDIM + bx * BN;
            #pragma unroll
            for (int nt = 0; nt < 4; nt++) {
                const int cl = wn * 32 + nt * 8 + 2 * tig;
                float v0 = d[mt][nt][hf * 2 + 0] * oscale;
                float v1 = d[mt][nt][hf * 2 + 1] * oscale;
                if (bias) { v0 += sbias[cl]; v1 += sbias[cl + 1]; }
                if (ACT == 1) { v0 = fmaxf(v0, 0.0f); v1 = fmaxf(v1, 0.0f); }
                if (ACT == 2) { v0 = tanhf(v0); v1 = tanhf(v1); }
                if (MODE == 0 || MODE == 1)
                    *(__half2*)(Ch + rc + cl) = __floats2half2_rn(v0, v1);
                if (MODE == 1 || MODE == 2)
                    *(float2*)(Cf + rc + cl) = make_float2(v0, v1);
            }
        }
    }
}

// ---------------- fused fp32 -> half conversion ------------------------------
__global__ void to_half_prep(const float4* __restrict__ a,  __half2* __restrict__ ah,
                             const float4* __restrict__ xs, __half2* __restrict__ xh,
                             const float4* __restrict__ wi, const float4* __restrict__ gw,
                             __half2* __restrict__ wh) {
    const int z = blockIdx.z;
    const float4* src; __half2* dst; int n4; float sc = 1.0f;
    if (z == 0) { src = a;  dst = ah; n4 = G * NNODE * NNODE / 4; sc = 1024.0f; }
    else if (z == 1) { src = xs; dst = xh; n4 = G * NNODE * FDIM / 4; }
    else if (z == 2) { src = wi; dst = wh; n4 = FDIM * HDIM / 4; }
    else { src = gw; dst = wh + FDIM * HDIM / 2; n4 = LAYERS * HDIM * HDIM / 4; }
    for (int i = blockIdx.x * blockDim.x + threadIdx.x; i < n4;
         i += gridDim.x * blockDim.x) {
        float4 v = src[i];
        dst[2 * i + 0] = __floats2half2_rn(v.x * sc, v.y * sc);
        dst[2 * i + 1] = __floats2half2_rn(v.z * sc, v.w * sc);
    }
}

// ---------------- masked mean + residual ------------------------------------
__global__ void reduce_kernel(const float* __restrict__ x,
                              const float* __restrict__ r,
                              const int* __restrict__ gidx,
                              const int* __restrict__ mask,
                              float* __restrict__ out) {
    const int b = blockIdx.x;
    const int h = threadIdx.x;
    const int g = gidx[b];
    const float* xb = x + (size_t)g * NNODE * HDIM;
    const float* rb = r + (size_t)g * NNODE * HDIM;
    const int* mb = mask + b * NNODE;

    float acc = 0.0f, cnt = 0.0f;
    #pragma unroll 8
    for (int n = 0; n < NNODE; n++) {
        float m = (mb[n] != 0) ? 1.0f : 0.0f;
        cnt += m;
        acc += m * (xb[(size_t)n * HDIM + h] + rb[(size_t)n * HDIM + h]);
    }
    out[b * HDIM + h] = acc / fmaxf(cnt, 1.0f);
}

// ---------------- launch -----------------------------------------------------
extern "C" void kernel_launch(void* const* d_in, const int* in_sizes, int n_in,
                              void* d_out, int out_size) {
    const float* batch_xs = (const float*)d_in[0];
    const float* batch_as = (const float*)d_in[1];
    const float* w_in     = (const float*)d_in[2];
    const float* b_in     = (const float*)d_in[3];
    const float* gcn_w    = (const float*)d_in[4];
    const float* gcn_b    = (const float*)d_in[5];
    const int*   gidx     = (const int*)d_in[6];
    const int*   cp_mask  = (const int*)d_in[7];
    float* out = (float*)d_out;

    __half *ah, *xin, *wh, *h0h, *th, *xh;
    float *h0f, *xl;
    cudaGetSymbolAddress((void**)&ah,  g_ah);
    cudaGetSymbolAddress((void**)&xin, g_xin);
    cudaGetSymbolAddress((void**)&wh,  g_wh);
    cudaGetSymbolAddress((void**)&h0h, g_h0h);
    cudaGetSymbolAddress((void**)&th,  g_th);
    cudaGetSymbolAddress((void**)&xh,  g_xh);
    cudaGetSymbolAddress((void**)&h0f, g_h0f);
    cudaGetSymbolAddress((void**)&xl,  g_xl);

    cudaFuncSetAttribute(tc_gemm<1, 1>, cudaFuncAttributeMaxDynamicSharedMemorySize, SMEM_BYTES);
    cudaFuncSetAttribute(tc_gemm<0, 0>, cudaFuncAttributeMaxDynamicSharedMemorySize, SMEM_BYTES);
    cudaFuncSetAttribute(tc_gemm<1, 0>, cudaFuncAttributeMaxDynamicSharedMemorySize, SMEM_BYTES);
    cudaFuncSetAttribute(tc_gemm<2, 2>, cudaFuncAttributeMaxDynamicSharedMemorySize, SMEM_BYTES);

    to_half_prep<<<dim3(2048, 1, 4), 256>>>(
        (const float4*)batch_as, (__half2*)ah,
        (const float4*)batch_xs, (__half2*)xin,
        (const float4*)w_in, (const float4*)gcn_w, (__half2*)wh);

    const int MG = G * NNODE;  // 4096
    const float inv1024 = 1.0f / 1024.0f;

    // input dense: h0 = relu(X @ w_in + b) -> fp32 (residual) + half (layer input)
    tc_gemm<1, 1><<<dim3(HDIM / BN, MG / BM, 1), 256, SMEM_BYTES>>>(
        xin, wh, b_in, h0h, h0f, FDIM, 0, 0, 0, 1.0f);

    const __half* cur = h0h;
    for (int i = 0; i < LAYERS; i++) {
        // t[g] = A[g] @ x[g]; adjacency pre-scaled x1024, undone by oscale
        tc_gemm<0, 0><<<dim3(HDIM / BN, NNODE / BM, G), 256, SMEM_BYTES>>>(
            ah, cur, nullptr, th, nullptr, NNODE,
            (long)NNODE * NNODE, (long)NNODE * HDIM, (long)NNODE * HDIM, inv1024);
        if (i < LAYERS - 1) {
            tc_gemm<1, 0><<<dim3(HDIM / BN, MG / BM, 1), 256, SMEM_BYTES>>>(
                th, wh + (size_t)(1 + i) * HDIM * HDIM, gcn_b + i * HDIM,
                xh, nullptr, HDIM, 0, 0, 0, 1.0f);
            cur = xh;
        } else {
            tc_gemm<2, 2><<<dim3(HDIM / BN, MG / BM, 1), 256, SMEM_BYTES>>>(
                th, wh + (size_t)LAYERS * HDIM * HDIM, gcn_b + (LAYERS - 1) * HDIM,
                nullptr, xl, HDIM, 0, 0, 0, 1.0f);
        }
    }

    reduce_kernel<<<BATCH, HDIM>>>(xl, h0f, gidx, cp_mask, out);
}

// round 6
// speedup vs baseline: 2.9688x; 1.0237x over previous
#include <cuda_runtime.h>
#include <cuda_fp16.h>
#include <math.h>
#include <stdint.h>

#define G 4
#define NNODE 1024
#define FDIM 256
#define HDIM 256
#define BATCH 32
#define LAYERS 4

// ---------------- scratch (device globals; no allocation allowed) -----------
__device__ __half g_ah [G * NNODE * NNODE];          // adjacency, half, x1024
__device__ __half g_xin[G * NNODE * FDIM];           // input feats, half
__device__ __half g_wh [(1 + LAYERS) * HDIM * HDIM]; // weights, half
__device__ __half g_h0h[G * NNODE * HDIM];           // h0 as half (GEMM input)
__device__ __half g_th [G * NNODE * HDIM];           // A @ x (half)
__device__ __half g_xh [G * NNODE * HDIM];           // hidden activations (half)
__device__ float  g_h0f[G * NNODE * HDIM];           // h0 fp32 (residual)
__device__ float  g_xl [G * NNODE * HDIM];           // final output fp32

// ---------------- tiling ----------------------------------------------------
#define BM 64
#define BN 128
#define BK 64
#define NSTAGE 4
#define PFD 3                             // prefetch distance (chunks ahead)
#define ASTR_H 72                         // A smem row stride in halves (144 B)
#define BSTR_H 136                        // B smem row stride in halves (272 B)
#define A_STG_B (BM * ASTR_H * 2)         // 9216 B
#define B_STG_B (BK * BSTR_H * 2)         // 17408 B
#define SM_BIAS_B 512
#define SMEM_BYTES (SM_BIAS_B + NSTAGE * (A_STG_B + B_STG_B))   // 106.9 KB

__device__ __forceinline__ uint32_t smem_u32(const void* p) {
    uint32_t a;
    asm("{ .reg .u64 t; cvta.to.shared.u64 t, %1; cvt.u32.u64 %0, t; }" : "=r"(a) : "l"(p));
    return a;
}
__device__ __forceinline__ void cpa16(uint32_t dst, const void* src) {
    asm volatile("cp.async.cg.shared.global [%0], [%1], 16;" :: "r"(dst), "l"(src));
}
#define CP_COMMIT() asm volatile("cp.async.commit_group;" ::: "memory")
#define CP_WAIT2()  asm volatile("cp.async.wait_group 2;" ::: "memory")

__device__ __forceinline__ void ldsm_x4(uint32_t* r, uint32_t addr) {
    asm volatile("ldmatrix.sync.aligned.m8n8.x4.shared.b16 {%0,%1,%2,%3}, [%4];"
        : "=r"(r[0]), "=r"(r[1]), "=r"(r[2]), "=r"(r[3]) : "r"(addr));
}
__device__ __forceinline__ void ldsm_x4_t(uint32_t* r, uint32_t addr) {
    asm volatile("ldmatrix.sync.aligned.m8n8.x4.trans.shared.b16 {%0,%1,%2,%3}, [%4];"
        : "=r"(r[0]), "=r"(r[1]), "=r"(r[2]), "=r"(r[3]) : "r"(addr));
}
__device__ __forceinline__ void mma_f16(float* d, const uint32_t* a, uint32_t b0, uint32_t b1) {
    asm volatile(
        "mma.sync.aligned.m16n8k16.row.col.f32.f16.f16.f32 "
        "{%0,%1,%2,%3}, {%4,%5,%6,%7}, {%8,%9}, {%0,%1,%2,%3};"
        : "+f"(d[0]), "+f"(d[1]), "+f"(d[2]), "+f"(d[3])
        : "r"(a[0]), "r"(a[1]), "r"(a[2]), "r"(a[3]), "r"(b0), "r"(b1));
}

// ---------------- fp16 mma.sync GEMM -----------------------------------------
// C = act(oscale * (A @ B) + bias)
// A [M,K] half row-major; B [K,256] half row-major; outputs row-major [.,256].
// ACT: 0 none, 1 relu, 2 tanh. MODE: 0 half out, 1 half+fp32 out, 2 fp32 out.
template <int ACT, int MODE>
__global__ void __launch_bounds__(256)
tc_gemm(const __half* __restrict__ A, const __half* __restrict__ B,
        const float* __restrict__ bias,
        __half* __restrict__ Ch, float* __restrict__ Cf,
        int K, long sAz, long sBz, long sCz, float oscale) {
    extern __shared__ char smraw[];
    float* sbias = (float*)smraw;                       // [BN]
    char* sA = smraw + SM_BIAS_B;                       // NSTAGE x A_STG_B
    char* sB = sA + NSTAGE * A_STG_B;                   // NSTAGE x B_STG_B
    const uint32_t uA = smem_u32(sA);
    const uint32_t uB = smem_u32(sB);

    const int tid = threadIdx.x;
    const int wid = tid >> 5, lane = tid & 31;
    const int wm = wid >> 2, wn = wid & 3;              // warps 2 (M) x 4 (N)
    const int gid = lane >> 2, tig = lane & 3;
    const int bx = blockIdx.x, by = blockIdx.y, bz = blockIdx.z;

    A += (long)bz * sAz + (long)(by * BM) * K;
    B += (long)bz * sBz + (long)bx * BN;

    if (bias && tid < BN) sbias[tid] = bias[bx * BN + tid];

    const int NC = K / BK;

    auto load_stage = [&](int c, int s) {
        const __half* Ag = A + c * BK;
        const __half* Bg = B + (long)(c * BK) * HDIM;
        uint32_t aBase = uA + s * A_STG_B;
        uint32_t bBase = uB + s * B_STG_B;
        #pragma unroll
        for (int i = 0; i < 2; i++) {                   // A: 64 rows x 8 x 16B
            int idx = tid + i * 256;
            int r = idx >> 3, q = idx & 7;
            cpa16(aBase + r * (ASTR_H * 2) + q * 16, Ag + (long)r * K + q * 8);
        }
        #pragma unroll
        for (int i = 0; i < 4; i++) {                   // B: 64 rows x 16 x 16B
            int idx = tid + i * 256;
            int r = idx >> 4, q = idx & 15;
            cpa16(bBase + r * (BSTR_H * 2) + q * 16, Bg + (long)r * HDIM + q * 8);
        }
    };

    // ldmatrix lane addresses (byte offsets inside a stage)
    const int l15 = lane & 15, l4 = lane >> 4;
    // A (non-trans): row = wm*32 + mt*16 + (lane&15); kblk16B = lane>>4
    const uint32_t aLane = (uint32_t)((wm * 32 + l15) * (ASTR_H * 2) + l4 * 16);
    // B (trans): row(k) = kstep*16 + (lane&15); col = wn*32 + pair*16 + (lane>>4)*8
    const uint32_t bLane = (uint32_t)(l15 * (BSTR_H * 2) + (wn * 32 + l4 * 8) * 2);

    float d[2][4][4] = {};

    // prologue: PFD stages in flight
    #pragma unroll
    for (int c = 0; c < PFD; c++) {
        if (c < NC) load_stage(c, c);
        CP_COMMIT();
    }

    for (int c = 0; c < NC; c++) {
        CP_WAIT2();                       // stage c complete (<=2 groups pending)
        __syncthreads();
        if (c + PFD < NC) load_stage(c + PFD, (c + PFD) % NSTAGE);
        CP_COMMIT();

        const int s = c % NSTAGE;
        const uint32_t aS = uA + s * A_STG_B + aLane;
        const uint32_t bS = uB + s * B_STG_B + bLane;

        #pragma unroll
        for (int ks = 0; ks < 4; ks++) {                // 4 x k16 per BK=64
            uint32_t a0[4], a1[4], bp0[4], bp1[4];
            ldsm_x4(a0, aS + ks * 32);                              // m 0..15
            ldsm_x4(a1, aS + ks * 32 + 16 * (ASTR_H * 2));          // m 16..31
            ldsm_x4_t(bp0, bS + ks * 16 * (BSTR_H * 2));            // n 0..15
            ldsm_x4_t(bp1, bS + ks * 16 * (BSTR_H * 2) + 32);       // n 16..31
            mma_f16(d[0][0], a0, bp0[0], bp0[1]);
            mma_f16(d[1][0], a1, bp0[0], bp0[1]);
            mma_f16(d[0][1], a0, bp0[2], bp0[3]);
            mma_f16(d[1][1], a1, bp0[2], bp0[3]);
            mma_f16(d[0][2], a0, bp1[0], bp1[1]);
            mma_f16(d[1][2], a1, bp1[0], bp1[1]);
            mma_f16(d[0][3], a0, bp1[2], bp1[3]);
            mma_f16(d[1][3], a1, bp1[2], bp1[3]);
        }
    }

    // epilogue
    #pragma unroll
    for (int mt = 0; mt < 2; mt++) {
        #pragma unroll
        for (int hf = 0; hf < 2; hf++) {
            const long row = (long)by * BM + wm * 32 + mt * 16 + gid + hf * 8;
            const long rc = (long)bz * sCz + row * HDIM + bx * BN;
            #pragma unroll
            for (int nt = 0; nt < 4; nt++) {
                const int cl = wn * 32 + nt * 8 + 2 * tig;
                float v0 = d[mt][nt][hf * 2 + 0] * oscale;
                float v1 = d[mt][nt][hf * 2 + 1] * oscale;
                if (bias) { v0 += sbias[cl]; v1 += sbias[cl + 1]; }
                if (ACT == 1) { v0 = fmaxf(v0, 0.0f); v1 = fmaxf(v1, 0.0f); }
                if (ACT == 2) { v0 = tanhf(v0); v1 = tanhf(v1); }
                if (MODE == 0 || MODE == 1)
                    *(__half2*)(Ch + rc + cl) = __floats2half2_rn(v0, v1);
                if (MODE == 1 || MODE == 2)
                    *(float2*)(Cf + rc + cl) = make_float2(v0, v1);
            }
        }
    }
}

// ---------------- fused fp32 -> half conversion ------------------------------
__global__ void to_half_prep(const float4* __restrict__ a,  __half2* __restrict__ ah,
                             const float4* __restrict__ xs, __half2* __restrict__ xh,
                             const float4* __restrict__ wi, const float4* __restrict__ gw,
                             __half2* __restrict__ wh) {
    const int z = blockIdx.z;
    const float4* src; __half2* dst; int n4; float sc = 1.0f;
    if (z == 0) { src = a;  dst = ah; n4 = G * NNODE * NNODE / 4; sc = 1024.0f; }
    else if (z == 1) { src = xs; dst = xh; n4 = G * NNODE * FDIM / 4; }
    else if (z == 2) { src = wi; dst = wh; n4 = FDIM * HDIM / 4; }
    else { src = gw; dst = wh + FDIM * HDIM / 2; n4 = LAYERS * HDIM * HDIM / 4; }
    for (int i = blockIdx.x * blockDim.x + threadIdx.x; i < n4;
         i += gridDim.x * blockDim.x) {
        float4 v = src[i];
        dst[2 * i + 0] = __floats2half2_rn(v.x * sc, v.y * sc);
        dst[2 * i + 1] = __floats2half2_rn(v.z * sc, v.w * sc);
    }
}

// ---------------- masked mean + residual ------------------------------------
__global__ void reduce_kernel(const float* __restrict__ x,
                              const float* __restrict__ r,
                              const int* __restrict__ gidx,
                              const int* __restrict__ mask,
                              float* __restrict__ out) {
    const int b = blockIdx.x;
    const int h = threadIdx.x;
    const int g = gidx[b];
    const float* xb = x + (size_t)g * NNODE * HDIM;
    const float* rb = r + (size_t)g * NNODE * HDIM;
    const int* mb = mask + b * NNODE;

    float acc = 0.0f, cnt = 0.0f;
    #pragma unroll 8
    for (int n = 0; n < NNODE; n++) {
        float m = (mb[n] != 0) ? 1.0f : 0.0f;
        cnt += m;
        acc += m * (xb[(size_t)n * HDIM + h] + rb[(size_t)n * HDIM + h]);
    }
    out[b * HDIM + h] = acc / fmaxf(cnt, 1.0f);
}

// ---------------- launch -----------------------------------------------------
extern "C" void kernel_launch(void* const* d_in, const int* in_sizes, int n_in,
                              void* d_out, int out_size) {
    const float* batch_xs = (const float*)d_in[0];
    const float* batch_as = (const float*)d_in[1];
    const float* w_in     = (const float*)d_in[2];
    const float* b_in     = (const float*)d_in[3];
    const float* gcn_w    = (const float*)d_in[4];
    const float* gcn_b    = (const float*)d_in[5];
    const int*   gidx     = (const int*)d_in[6];
    const int*   cp_mask  = (const int*)d_in[7];
    float* out = (float*)d_out;

    __half *ah, *xin, *wh, *h0h, *th, *xh;
    float *h0f, *xl;
    cudaGetSymbolAddress((void**)&ah,  g_ah);
    cudaGetSymbolAddress((void**)&xin, g_xin);
    cudaGetSymbolAddress((void**)&wh,  g_wh);
    cudaGetSymbolAddress((void**)&h0h, g_h0h);
    cudaGetSymbolAddress((void**)&th,  g_th);
    cudaGetSymbolAddress((void**)&xh,  g_xh);
    cudaGetSymbolAddress((void**)&h0f, g_h0f);
    cudaGetSymbolAddress((void**)&xl,  g_xl);

    cudaFuncSetAttribute(tc_gemm<1, 1>, cudaFuncAttributeMaxDynamicSharedMemorySize, SMEM_BYTES);
    cudaFuncSetAttribute(tc_gemm<0, 0>, cudaFuncAttributeMaxDynamicSharedMemorySize, SMEM_BYTES);
    cudaFuncSetAttribute(tc_gemm<1, 0>, cudaFuncAttributeMaxDynamicSharedMemorySize, SMEM_BYTES);
    cudaFuncSetAttribute(tc_gemm<2, 2>, cudaFuncAttributeMaxDynamicSharedMemorySize, SMEM_BYTES);

    to_half_prep<<<dim3(2048, 1, 4), 256>>>(
        (const float4*)batch_as, (__half2*)ah,
        (const float4*)batch_xs, (__half2*)xin,
        (const float4*)w_in, (const float4*)gcn_w, (__half2*)wh);

    const int MG = G * NNODE;  // 4096
    const float inv1024 = 1.0f / 1024.0f;

    // input dense: h0 = relu(X @ w_in + b) -> fp32 (residual) + half (layer input)
    tc_gemm<1, 1><<<dim3(HDIM / BN, MG / BM, 1), 256, SMEM_BYTES>>>(
        xin, wh, b_in, h0h, h0f, FDIM, 0, 0, 0, 1.0f);

    const __half* cur = h0h;
    for (int i = 0; i < LAYERS; i++) {
        // t[g] = A[g] @ x[g]; adjacency pre-scaled x1024, undone by oscale
        tc_gemm<0, 0><<<dim3(HDIM / BN, NNODE / BM, G), 256, SMEM_BYTES>>>(
            ah, cur, nullptr, th, nullptr, NNODE,
            (long)NNODE * NNODE, (long)NNODE * HDIM, (long)NNODE * HDIM, inv1024);
        if (i < LAYERS - 1) {
            tc_gemm<1, 0><<<dim3(HDIM / BN, MG / BM, 1), 256, SMEM_BYTES>>>(
                th, wh + (size_t)(1 + i) * HDIM * HDIM, gcn_b + i * HDIM,
                xh, nullptr, HDIM, 0, 0, 0, 1.0f);
            cur = xh;
        } else {
            tc_gemm<2, 2><<<dim3(HDIM / BN, MG / BM, 1), 256, SMEM_BYTES>>>(
                th, wh + (size_t)LAYERS * HDIM * HDIM, gcn_b + (LAYERS - 1) * HDIM,
                nullptr, xl, HDIM, 0, 0, 0, 1.0f);
        }
    }

    reduce_kernel<<<BATCH, HDIM>>>(xl, h0f, gidx, cp_mask, out);
}

// round 7
// speedup vs baseline: 4.5246x; 1.5240x over previous
#include <cuda_runtime.h>
#include <cuda_fp16.h>
#include <math.h>
#include <stdint.h>

#define G 4
#define NNODE 1024
#define FDIM 256
#define HDIM 256
#define BATCH 32
#define LAYERS 4
#define NCTA 128
#define NTHR 256

// ---------------- scratch (device globals; no allocation allowed) -----------
__device__ __half g_ah [G * NNODE * NNODE];          // adjacency, half, x1024
__device__ __half g_xin[G * NNODE * FDIM];           // input feats, half
__device__ __half g_wh [(1 + LAYERS) * HDIM * HDIM]; // weights, half
__device__ __half g_h0h[G * NNODE * HDIM];           // h0 as half (GEMM input)
__device__ __half g_th [G * NNODE * HDIM];           // A @ x (half)
__device__ __half g_xh [G * NNODE * HDIM];           // hidden activations (half)
__device__ float  g_h0f[G * NNODE * HDIM];           // h0 fp32 (residual)
__device__ float  g_xl [G * NNODE * HDIM];           // final output fp32
__device__ float  g_part[BATCH * 4 * HDIM];          // reduce partials
__device__ float  g_cnt [BATCH * 4];                 // reduce counts
__device__ unsigned g_bar_epoch;                     // barrier epoch (monotone)
__device__ unsigned g_bar_count;                     // barrier arrive counter

// ---------------- tiling ----------------------------------------------------
#define BM 64
#define BN 128
#define BK 64
#define NSTAGE 3
#define PFD 2
#define ASTR_H 72
#define BSTR_H 136
#define A_STG_B (BM * ASTR_H * 2)         // 9216 B
#define B_STG_B (BK * BSTR_H * 2)         // 17408 B
#define SM_BIAS_B 512
#define SMEM_BYTES (SM_BIAS_B + NSTAGE * (A_STG_B + B_STG_B))   // 80384 B

__device__ __forceinline__ uint32_t smem_u32(const void* p) {
    uint32_t a;
    asm("{ .reg .u64 t; cvta.to.shared.u64 t, %1; cvt.u32.u64 %0, t; }" : "=r"(a) : "l"(p));
    return a;
}
__device__ __forceinline__ void cpa16(uint32_t dst, const void* src) {
    asm volatile("cp.async.cg.shared.global [%0], [%1], 16;" :: "r"(dst), "l"(src));
}
#define CP_COMMIT() asm volatile("cp.async.commit_group;" ::: "memory")
#define CP_WAIT1()  asm volatile("cp.async.wait_group 1;" ::: "memory")
#define CP_WAIT0()  asm volatile("cp.async.wait_group 0;" ::: "memory")

__device__ __forceinline__ void ldsm_x4(uint32_t* r, uint32_t addr) {
    asm volatile("ldmatrix.sync.aligned.m8n8.x4.shared.b16 {%0,%1,%2,%3}, [%4];"
        : "=r"(r[0]), "=r"(r[1]), "=r"(r[2]), "=r"(r[3]) : "r"(addr));
}
__device__ __forceinline__ void ldsm_x4_t(uint32_t* r, uint32_t addr) {
    asm volatile("ldmatrix.sync.aligned.m8n8.x4.trans.shared.b16 {%0,%1,%2,%3}, [%4];"
        : "=r"(r[0]), "=r"(r[1]), "=r"(r[2]), "=r"(r[3]) : "r"(addr));
}
__device__ __forceinline__ void mma_f16(float* d, const uint32_t* a, uint32_t b0, uint32_t b1) {
    asm volatile(
        "mma.sync.aligned.m16n8k16.row.col.f32.f16.f16.f32 "
        "{%0,%1,%2,%3}, {%4,%5,%6,%7}, {%8,%9}, {%0,%1,%2,%3};"
        : "+f"(d[0]), "+f"(d[1]), "+f"(d[2]), "+f"(d[3])
        : "r"(a[0]), "r"(a[1]), "r"(a[2]), "r"(a[3]), "r"(b0), "r"(b1));
}

// ---------------- device-wide barrier (all CTAs resident: 128 <= 148 SMs) ---
__device__ __forceinline__ void grid_barrier(unsigned target) {
    __syncthreads();
    if (threadIdx.x == 0) {
        __threadfence();
        unsigned old = atomicAdd(&g_bar_count, 1u);
        if (old == NCTA - 1) {
            atomicExch(&g_bar_count, 0u);
            __threadfence();
            atomicAdd(&g_bar_epoch, 1u);
        } else {
            unsigned e;
            do {
                asm volatile("ld.acquire.gpu.u32 %0, [%1];"
                             : "=r"(e) : "l"(&g_bar_epoch));
                if ((int)(e - target) >= 0) break;
                __nanosleep(32);
            } while (true);
        }
    }
    __syncthreads();
}

// ---------------- fp16 mma.sync GEMM phase -----------------------------------
// C = act(oscale * (A @ B) + bias). A,B,C pre-offset by z-batch by caller.
// ACT: 0 none, 1 relu, 2 tanh. MODE: 0 half out, 1 half+fp32 out, 2 fp32 out.
template <int ACT, int MODE>
__device__ void gemm_phase(char* smraw,
        const __half* A, const __half* B, const float* bias,
        __half* Ch, float* Cf, int K, float oscale, int bx, int by) {
    float* sbias = (float*)smraw;
    char* sA = smraw + SM_BIAS_B;
    char* sB = sA + NSTAGE * A_STG_B;
    const uint32_t uA = smem_u32(sA);
    const uint32_t uB = smem_u32(sB);

    const int tid = threadIdx.x;
    const int wid = tid >> 5, lane = tid & 31;
    const int wm = wid >> 2, wn = wid & 3;
    const int gid = lane >> 2, tig = lane & 3;

    A += (long)(by * BM) * K;
    B += (long)bx * BN;

    if (bias && tid < BN) sbias[tid] = bias[bx * BN + tid];

    const int NC = K / BK;

    auto load_stage = [&](int c, int s) {
        const __half* Ag = A + c * BK;
        const __half* Bg = B + (long)(c * BK) * HDIM;
        uint32_t aBase = uA + s * A_STG_B;
        uint32_t bBase = uB + s * B_STG_B;
        #pragma unroll
        for (int i = 0; i < 2; i++) {
            int idx = tid + i * 256;
            int r = idx >> 3, q = idx & 7;
            cpa16(aBase + r * (ASTR_H * 2) + q * 16, Ag + (long)r * K + q * 8);
        }
        #pragma unroll
        for (int i = 0; i < 4; i++) {
            int idx = tid + i * 256;
            int r = idx >> 4, q = idx & 15;
            cpa16(bBase + r * (BSTR_H * 2) + q * 16, Bg + (long)r * HDIM + q * 8);
        }
    };

    const int l15 = lane & 15, l4 = lane >> 4;
    const uint32_t aLane = (uint32_t)((wm * 32 + l15) * (ASTR_H * 2) + l4 * 16);
    const uint32_t bLane = (uint32_t)(l15 * (BSTR_H * 2) + (wn * 32 + l4 * 8) * 2);

    float d[2][4][4] = {};

    load_stage(0, 0); CP_COMMIT();
    if (NC > 1) load_stage(1, 1);
    CP_COMMIT();

    for (int c = 0; c < NC; c++) {
        CP_WAIT1();
        __syncthreads();
        if (c + PFD < NC) load_stage(c + PFD, (c + PFD) % NSTAGE);
        CP_COMMIT();

        const int s = c % NSTAGE;
        const uint32_t aS = uA + s * A_STG_B + aLane;
        const uint32_t bS = uB + s * B_STG_B + bLane;

        #pragma unroll
        for (int ks = 0; ks < 4; ks++) {
            uint32_t a0[4], a1[4], bp0[4], bp1[4];
            ldsm_x4(a0, aS + ks * 32);
            ldsm_x4(a1, aS + ks * 32 + 16 * (ASTR_H * 2));
            ldsm_x4_t(bp0, bS + ks * 16 * (BSTR_H * 2));
            ldsm_x4_t(bp1, bS + ks * 16 * (BSTR_H * 2) + 32);
            mma_f16(d[0][0], a0, bp0[0], bp0[1]);
            mma_f16(d[1][0], a1, bp0[0], bp0[1]);
            mma_f16(d[0][1], a0, bp0[2], bp0[3]);
            mma_f16(d[1][1], a1, bp0[2], bp0[3]);
            mma_f16(d[0][2], a0, bp1[0], bp1[1]);
            mma_f16(d[1][2], a1, bp1[0], bp1[1]);
            mma_f16(d[0][3], a0, bp1[2], bp1[3]);
            mma_f16(d[1][3], a1, bp1[2], bp1[3]);
        }
    }
    CP_WAIT0();

    #pragma unroll
    for (int mt = 0; mt < 2; mt++) {
        #pragma unroll
        for (int hf = 0; hf < 2; hf++) {
            const long row = (long)by * BM + wm * 32 + mt * 16 + gid + hf * 8;
            const long rc = row * HDIM + bx * BN;
            #pragma unroll
            for (int nt = 0; nt < 4; nt++) {
                const int cl = wn * 32 + nt * 8 + 2 * tig;
                float v0 = d[mt][nt][hf * 2 + 0] * oscale;
                float v1 = d[mt][nt][hf * 2 + 1] * oscale;
                if (bias) { v0 += sbias[cl]; v1 += sbias[cl + 1]; }
                if (ACT == 1) { v0 = fmaxf(v0, 0.0f); v1 = fmaxf(v1, 0.0f); }
                if (ACT == 2) { v0 = tanhf(v0); v1 = tanhf(v1); }
                if (MODE == 0 || MODE == 1)
                    *(__half2*)(Ch + rc + cl) = __floats2half2_rn(v0, v1);
                if (MODE == 1 || MODE == 2)
                    *(float2*)(Cf + rc + cl) = make_float2(v0, v1);
            }
        }
    }
}

// ---------------- the megakernel --------------------------------------------
#define TOT4_A (G * NNODE * NNODE / 4)
#define TOT4_X (G * NNODE * FDIM / 4)
#define TOT4_W ((1 + LAYERS) * HDIM * HDIM / 4)
#define TOT4_WIN (FDIM * HDIM / 4)

__global__ void __launch_bounds__(NTHR)
meganet(const float* batch_xs, const float* batch_as,
        const float* w_in, const float* b_in,
        const float* gcn_w, const float* gcn_b,
        const int* gidx, const int* mask, float* out) {
    extern __shared__ char smraw[];
    const int cta = blockIdx.x;
    const int tid = threadIdx.x;
    const unsigned e0 = g_bar_epoch;   // epoch snapshot (pre-barrier, all CTAs)
    unsigned bt = e0;

    __half* ah  = g_ah;
    __half* xin = g_xin;
    __half* wh  = g_wh;

    // ---- phase P: fp32 -> half conversion (grid-stride over all inputs) ----
    {
        const float4* a4 = (const float4*)batch_as;
        const float4* x4 = (const float4*)batch_xs;
        const float4* wi = (const float4*)w_in;
        const float4* gw = (const float4*)gcn_w;
        __half2* ah2 = (__half2*)ah;
        __half2* xh2 = (__half2*)xin;
        __half2* wh2 = (__half2*)wh;
        const int total = TOT4_A + TOT4_X + TOT4_W;
        for (int i = cta * NTHR + tid; i < total; i += NCTA * NTHR) {
            float4 v; __half2* dst; float sc = 1.0f;
            if (i < TOT4_A) {
                v = a4[i]; dst = ah2 + 2 * i; sc = 1024.0f;
            } else if (i < TOT4_A + TOT4_X) {
                int j = i - TOT4_A;
                v = x4[j]; dst = xh2 + 2 * j;
            } else {
                int j = i - TOT4_A - TOT4_X;
                if (j < TOT4_WIN) { v = wi[j]; dst = wh2 + 2 * j; }
                else { v = gw[j - TOT4_WIN]; dst = wh2 + 2 * j; }
            }
            dst[0] = __floats2half2_rn(v.x * sc, v.y * sc);
            dst[1] = __floats2half2_rn(v.z * sc, v.w * sc);
        }
    }
    grid_barrier(++bt);

    // ---- phase 0: h0 = relu(X @ w_in + b_in)  (2 x 64 tiles) ----
    gemm_phase<1, 1>(smraw, xin, wh, b_in, g_h0h, g_h0f,
                     FDIM, 1.0f, cta & 1, cta >> 1);
    grid_barrier(++bt);

    const float inv1024 = 1.0f / 1024.0f;
    const __half* cur = g_h0h;
    for (int i = 0; i < LAYERS; i++) {
        // t[g] = A[g] @ x[g]   (2 x 16 x 4 tiles)
        {
            const int bx = cta & 1, by = (cta >> 1) & 15, bz = cta >> 5;
            gemm_phase<0, 0>(smraw,
                ah + (long)bz * NNODE * NNODE,
                cur + (long)bz * NNODE * HDIM, nullptr,
                g_th + (long)bz * NNODE * HDIM, nullptr,
                NNODE, inv1024, bx, by);
        }
        grid_barrier(++bt);
        // x = act(t @ W_i + b_i)  (2 x 64 tiles)
        if (i < LAYERS - 1) {
            gemm_phase<1, 0>(smraw, g_th, wh + (size_t)(1 + i) * HDIM * HDIM,
                             gcn_b + i * HDIM, g_xh, nullptr,
                             HDIM, 1.0f, cta & 1, cta >> 1);
            cur = g_xh;
        } else {
            gemm_phase<2, 2>(smraw, g_th, wh + (size_t)LAYERS * HDIM * HDIM,
                             gcn_b + (LAYERS - 1) * HDIM, nullptr, g_xl,
                             HDIM, 1.0f, cta & 1, cta >> 1);
        }
        grid_barrier(++bt);
    }

    // ---- phase R1: partial masked sums (128 CTAs: b = cta>>2, slice = cta&3)
    {
        const int b = cta >> 2, s = cta & 3;
        const int g = gidx[b];
        const float* xb = g_xl  + (size_t)g * NNODE * HDIM;
        const float* rb = g_h0f + (size_t)g * NNODE * HDIM;
        const int* mb = mask + b * NNODE;
        const int h = tid;
        float acc = 0.0f, cnt = 0.0f;
        #pragma unroll 4
        for (int n = s * 256; n < s * 256 + 256; n++) {
            float m = (mb[n] != 0) ? 1.0f : 0.0f;
            cnt += m;
            acc += m * (xb[(size_t)n * HDIM + h] + rb[(size_t)n * HDIM + h]);
        }
        g_part[(b * 4 + s) * HDIM + h] = acc;
        if (tid == 0) g_cnt[b * 4 + s] = cnt;
    }
    grid_barrier(++bt);

    // ---- phase R2: combine (32 CTAs) ----
    if (cta < BATCH) {
        const int b = cta, h = tid;
        float acc = 0.0f, cnt = 0.0f;
        #pragma unroll
        for (int s = 0; s < 4; s++) {
            acc += g_part[(b * 4 + s) * HDIM + h];
            cnt += g_cnt[b * 4 + s];
        }
        out[b * HDIM + h] = acc / fmaxf(cnt, 1.0f);
    }
}

// ---------------- launch -----------------------------------------------------
extern "C" void kernel_launch(void* const* d_in, const int* in_sizes, int n_in,
                              void* d_out, int out_size) {
    const float* batch_xs = (const float*)d_in[0];
    const float* batch_as = (const float*)d_in[1];
    const float* w_in     = (const float*)d_in[2];
    const float* b_in     = (const float*)d_in[3];
    const float* gcn_w    = (const float*)d_in[4];
    const float* gcn_b    = (const float*)d_in[5];
    const int*   gidx     = (const int*)d_in[6];
    const int*   cp_mask  = (const int*)d_in[7];
    float* out = (float*)d_out;

    static int attr_set = 0;
    cudaFuncSetAttribute(meganet, cudaFuncAttributeMaxDynamicSharedMemorySize,
                         SMEM_BYTES);
    (void)attr_set;

    meganet<<<NCTA, NTHR, SMEM_BYTES>>>(batch_xs, batch_as, w_in, b_in,
                                        gcn_w, gcn_b, gidx, cp_mask, out);
}

// round 8
// speedup vs baseline: 5.0948x; 1.1260x over previous
#include <cuda_runtime.h>
#include <cuda_fp16.h>
#include <math.h>
#include <stdint.h>

#define G 4
#define NNODE 1024
#define FDIM 256
#define HDIM 256
#define BATCH 32
#define LAYERS 4
#define NCTA 256
#define NTHR 256

// ---------------- scratch (device globals; no allocation allowed) -----------
__device__ __half g_ah [G * NNODE * NNODE];          // adjacency, half, x1024
__device__ __half g_xin[G * NNODE * FDIM];           // input feats, half
__device__ __half g_wh [(1 + LAYERS) * HDIM * HDIM]; // weights, half
__device__ __half g_h0h[G * NNODE * HDIM];           // h0 as half (GEMM input)
__device__ __half g_th [G * NNODE * HDIM];           // A @ x (half)
__device__ __half g_xh [G * NNODE * HDIM];           // hidden activations (half)
__device__ float  g_h0f[G * NNODE * HDIM];           // h0 fp32 (residual)
__device__ float  g_xl [G * NNODE * HDIM];           // final output fp32
__device__ float  g_part[BATCH * 8 * HDIM];          // reduce partials
__device__ float  g_cnt [BATCH * 8];                 // reduce counts
__device__ unsigned g_bar_epoch;                     // barrier epoch (monotone)
__device__ unsigned g_bar_count;                     // barrier arrive counter

// ---------------- tiling ----------------------------------------------------
#define BM 64
#define BN 64
#define BK 64
#define NSTAGE 3
#define PFD 2
#define ASTR_H 72
#define BSTR_H 72
#define A_STG_B (BM * ASTR_H * 2)         // 9216 B
#define B_STG_B (BK * BSTR_H * 2)         // 9216 B
#define SM_BIAS_B 512
#define SMEM_BYTES (SM_BIAS_B + NSTAGE * (A_STG_B + B_STG_B))   // 55808 B

__device__ __forceinline__ uint32_t smem_u32(const void* p) {
    uint32_t a;
    asm("{ .reg .u64 t; cvta.to.shared.u64 t, %1; cvt.u32.u64 %0, t; }" : "=r"(a) : "l"(p));
    return a;
}
__device__ __forceinline__ void cpa16(uint32_t dst, const void* src) {
    asm volatile("cp.async.cg.shared.global [%0], [%1], 16;" :: "r"(dst), "l"(src));
}
#define CP_COMMIT() asm volatile("cp.async.commit_group;" ::: "memory")
#define CP_WAIT1()  asm volatile("cp.async.wait_group 1;" ::: "memory")
#define CP_WAIT0()  asm volatile("cp.async.wait_group 0;" ::: "memory")

__device__ __forceinline__ void ldsm_x4(uint32_t* r, uint32_t addr) {
    asm volatile("ldmatrix.sync.aligned.m8n8.x4.shared.b16 {%0,%1,%2,%3}, [%4];"
        : "=r"(r[0]), "=r"(r[1]), "=r"(r[2]), "=r"(r[3]) : "r"(addr));
}
__device__ __forceinline__ void ldsm_x4_t(uint32_t* r, uint32_t addr) {
    asm volatile("ldmatrix.sync.aligned.m8n8.x4.trans.shared.b16 {%0,%1,%2,%3}, [%4];"
        : "=r"(r[0]), "=r"(r[1]), "=r"(r[2]), "=r"(r[3]) : "r"(addr));
}
__device__ __forceinline__ void mma_f16(float* d, const uint32_t* a, uint32_t b0, uint32_t b1) {
    asm volatile(
        "mma.sync.aligned.m16n8k16.row.col.f32.f16.f16.f32 "
        "{%0,%1,%2,%3}, {%4,%5,%6,%7}, {%8,%9}, {%0,%1,%2,%3};"
        : "+f"(d[0]), "+f"(d[1]), "+f"(d[2]), "+f"(d[3])
        : "r"(a[0]), "r"(a[1]), "r"(a[2]), "r"(a[3]), "r"(b0), "r"(b1));
}

// ---------------- device-wide barrier (all 256 CTAs resident: 2/SM) ---------
__device__ __forceinline__ void grid_barrier(unsigned target) {
    __syncthreads();
    if (threadIdx.x == 0) {
        __threadfence();
        unsigned old = atomicAdd(&g_bar_count, 1u);
        if (old == NCTA - 1) {
            atomicExch(&g_bar_count, 0u);
            __threadfence();
            atomicAdd(&g_bar_epoch, 1u);
        } else {
            unsigned e;
            do {
                asm volatile("ld.acquire.gpu.u32 %0, [%1];"
                             : "=r"(e) : "l"(&g_bar_epoch));
                if ((int)(e - target) >= 0) break;
                __nanosleep(32);
            } while (true);
        }
    }
    __syncthreads();
}

// ---------------- fp16 mma.sync GEMM phase -----------------------------------
// C = act(oscale * (A @ B) + bias). 64x64 tile, warp grid 2(M) x 4(N), warp 32x16.
// ACT: 0 none, 1 relu, 2 tanh. MODE: 0 half out, 1 half+fp32 out, 2 fp32 out.
template <int ACT, int MODE>
__device__ void gemm_phase(char* smraw,
        const __half* A, const __half* B, const float* bias,
        __half* Ch, float* Cf, int K, float oscale, int bx, int by) {
    float* sbias = (float*)smraw;
    char* sA = smraw + SM_BIAS_B;
    char* sB = sA + NSTAGE * A_STG_B;
    const uint32_t uA = smem_u32(sA);
    const uint32_t uB = smem_u32(sB);

    const int tid = threadIdx.x;
    const int wid = tid >> 5, lane = tid & 31;
    const int wm = wid >> 2, wn = wid & 3;
    const int gid = lane >> 2, tig = lane & 3;

    A += (long)(by * BM) * K;
    B += (long)bx * BN;

    if (bias && tid < BN) sbias[tid] = bias[bx * BN + tid];

    const int NC = K / BK;

    auto load_stage = [&](int c, int s) {
        const __half* Ag = A + c * BK;
        const __half* Bg = B + (long)(c * BK) * HDIM;
        uint32_t aBase = uA + s * A_STG_B;
        uint32_t bBase = uB + s * B_STG_B;
        #pragma unroll
        for (int i = 0; i < 2; i++) {                // A: 64 rows x 8 x 16B
            int idx = tid + i * 256;
            int r = idx >> 3, q = idx & 7;
            cpa16(aBase + r * (ASTR_H * 2) + q * 16, Ag + (long)r * K + q * 8);
        }
        #pragma unroll
        for (int i = 0; i < 2; i++) {                // B: 64 rows x 8 x 16B
            int idx = tid + i * 256;
            int r = idx >> 3, q = idx & 7;
            cpa16(bBase + r * (BSTR_H * 2) + q * 16, Bg + (long)r * HDIM + q * 8);
        }
    };

    const int l15 = lane & 15, l4 = lane >> 4;
    const uint32_t aLane = (uint32_t)((wm * 32 + l15) * (ASTR_H * 2) + l4 * 16);
    const uint32_t bLane = (uint32_t)(l15 * (BSTR_H * 2) + (wn * 16 + l4 * 8) * 2);

    float d[2][2][4] = {};

    load_stage(0, 0); CP_COMMIT();
    if (NC > 1) load_stage(1, 1);
    CP_COMMIT();

    for (int c = 0; c < NC; c++) {
        CP_WAIT1();
        __syncthreads();
        if (c + PFD < NC) load_stage(c + PFD, (c + PFD) % NSTAGE);
        CP_COMMIT();

        const int s = c % NSTAGE;
        const uint32_t aS = uA + s * A_STG_B + aLane;
        const uint32_t bS = uB + s * B_STG_B + bLane;

        #pragma unroll
        for (int ks = 0; ks < 4; ks++) {
            uint32_t a0[4], a1[4], bp[4];
            ldsm_x4(a0, aS + ks * 32);                          // m 0..15
            ldsm_x4(a1, aS + ks * 32 + 16 * (ASTR_H * 2));      // m 16..31
            ldsm_x4_t(bp, bS + ks * 16 * (BSTR_H * 2));         // n 0..15
            mma_f16(d[0][0], a0, bp[0], bp[1]);
            mma_f16(d[1][0], a1, bp[0], bp[1]);
            mma_f16(d[0][1], a0, bp[2], bp[3]);
            mma_f16(d[1][1], a1, bp[2], bp[3]);
        }
    }
    CP_WAIT0();

    #pragma unroll
    for (int mt = 0; mt < 2; mt++) {
        #pragma unroll
        for (int hf = 0; hf < 2; hf++) {
            const long row = (long)by * BM + wm * 32 + mt * 16 + gid + hf * 8;
            const long rc = row * HDIM + bx * BN;
            #pragma unroll
            for (int nt = 0; nt < 2; nt++) {
                const int cl = wn * 16 + nt * 8 + 2 * tig;
                float v0 = d[mt][nt][hf * 2 + 0] * oscale;
                float v1 = d[mt][nt][hf * 2 + 1] * oscale;
                if (bias) { v0 += sbias[cl]; v1 += sbias[cl + 1]; }
                if (ACT == 1) { v0 = fmaxf(v0, 0.0f); v1 = fmaxf(v1, 0.0f); }
                if (ACT == 2) { v0 = tanhf(v0); v1 = tanhf(v1); }
                if (MODE == 0 || MODE == 1)
                    *(__half2*)(Ch + rc + cl) = __floats2half2_rn(v0, v1);
                if (MODE == 1 || MODE == 2)
                    *(float2*)(Cf + rc + cl) = make_float2(v0, v1);
            }
        }
    }
}

// ---------------- the megakernel --------------------------------------------
#define TOT4_A (G * NNODE * NNODE / 4)
#define TOT4_X (G * NNODE * FDIM / 4)
#define TOT4_W ((1 + LAYERS) * HDIM * HDIM / 4)
#define TOT4_WIN (FDIM * HDIM / 4)

__global__ void __launch_bounds__(NTHR, 2)
meganet(const float* batch_xs, const float* batch_as,
        const float* w_in, const float* b_in,
        const float* gcn_w, const float* gcn_b,
        const int* gidx, const int* mask, float* out) {
    extern __shared__ char smraw[];
    const int cta = blockIdx.x;
    const int tid = threadIdx.x;
    unsigned bt = g_bar_epoch;   // epoch snapshot (pre-barrier, all CTAs)

    __half* ah  = g_ah;
    __half* xin = g_xin;
    __half* wh  = g_wh;

    // ---- phase P: fp32 -> half conversion (grid-stride over all inputs) ----
    {
        const float4* a4 = (const float4*)batch_as;
        const float4* x4 = (const float4*)batch_xs;
        const float4* wi = (const float4*)w_in;
        const float4* gw = (const float4*)gcn_w;
        __half2* ah2 = (__half2*)ah;
        __half2* xh2 = (__half2*)xin;
        __half2* wh2 = (__half2*)wh;
        const int total = TOT4_A + TOT4_X + TOT4_W;
        for (int i = cta * NTHR + tid; i < total; i += NCTA * NTHR) {
            float4 v; __half2* dst; float sc = 1.0f;
            if (i < TOT4_A) {
                v = a4[i]; dst = ah2 + 2 * i; sc = 1024.0f;
            } else if (i < TOT4_A + TOT4_X) {
                int j = i - TOT4_A;
                v = x4[j]; dst = xh2 + 2 * j;
            } else {
                int j = i - TOT4_A - TOT4_X;
                if (j < TOT4_WIN) { v = wi[j]; dst = wh2 + 2 * j; }
                else { v = gw[j - TOT4_WIN]; dst = wh2 + 2 * j; }
            }
            dst[0] = __floats2half2_rn(v.x * sc, v.y * sc);
            dst[1] = __floats2half2_rn(v.z * sc, v.w * sc);
        }
    }
    grid_barrier(++bt);

    // ---- phase 0: h0 = relu(X @ w_in + b_in)  (4 x 64 tiles) ----
    gemm_phase<1, 1>(smraw, xin, wh, b_in, g_h0h, g_h0f,
                     FDIM, 1.0f, cta & 3, cta >> 2);
    grid_barrier(++bt);

    const float inv1024 = 1.0f / 1024.0f;
    const __half* cur = g_h0h;
    for (int i = 0; i < LAYERS; i++) {
        // t[g] = A[g] @ x[g]   (4 x 16 x 4 tiles)
        {
            const int bx = cta & 3, by = (cta >> 2) & 15, bz = cta >> 6;
            gemm_phase<0, 0>(smraw,
                ah + (long)bz * NNODE * NNODE,
                cur + (long)bz * NNODE * HDIM, nullptr,
                g_th + (long)bz * NNODE * HDIM, nullptr,
                NNODE, inv1024, bx, by);
        }
        grid_barrier(++bt);
        // x = act(t @ W_i + b_i)  (4 x 64 tiles)
        if (i < LAYERS - 1) {
            gemm_phase<1, 0>(smraw, g_th, wh + (size_t)(1 + i) * HDIM * HDIM,
                             gcn_b + i * HDIM, g_xh, nullptr,
                             HDIM, 1.0f, cta & 3, cta >> 2);
            cur = g_xh;
        } else {
            gemm_phase<2, 2>(smraw, g_th, wh + (size_t)LAYERS * HDIM * HDIM,
                             gcn_b + (LAYERS - 1) * HDIM, nullptr, g_xl,
                             HDIM, 1.0f, cta & 3, cta >> 2);
        }
        grid_barrier(++bt);
    }

    // ---- phase R1: partial masked sums (256 CTAs: b = cta>>3, slice = cta&7)
    {
        const int b = cta >> 3, s = cta & 7;
        const int g = gidx[b];
        const float* xb = g_xl  + (size_t)g * NNODE * HDIM;
        const float* rb = g_h0f + (size_t)g * NNODE * HDIM;
        const int* mb = mask + b * NNODE;
        const int h = tid;
        float acc = 0.0f, cnt = 0.0f;
        #pragma unroll 4
        for (int n = s * 128; n < s * 128 + 128; n++) {
            float m = (mb[n] != 0) ? 1.0f : 0.0f;
            cnt += m;
            acc += m * (xb[(size_t)n * HDIM + h] + rb[(size_t)n * HDIM + h]);
        }
        g_part[(b * 8 + s) * HDIM + h] = acc;
        if (tid == 0) g_cnt[b * 8 + s] = cnt;
    }
    grid_barrier(++bt);

    // ---- phase R2: combine (32 CTAs) ----
    if (cta < BATCH) {
        const int b = cta, h = tid;
        float acc = 0.0f, cnt = 0.0f;
        #pragma unroll
        for (int s = 0; s < 8; s++) {
            acc += g_part[(b * 8 + s) * HDIM + h];
            cnt += g_cnt[b * 8 + s];
        }
        out[b * HDIM + h] = acc / fmaxf(cnt, 1.0f);
    }
}

// ---------------- launch -----------------------------------------------------
extern "C" void kernel_launch(void* const* d_in, const int* in_sizes, int n_in,
                              void* d_out, int out_size) {
    const float* batch_xs = (const float*)d_in[0];
    const float* batch_as = (const float*)d_in[1];
    const float* w_in     = (const float*)d_in[2];
    const float* b_in     = (const float*)d_in[3];
    const float* gcn_w    = (const float*)d_in[4];
    const float* gcn_b    = (const float*)d_in[5];
    const int*   gidx     = (const int*)d_in[6];
    const int*   cp_mask  = (const int*)d_in[7];
    float* out = (float*)d_out;

    cudaFuncSetAttribute(meganet, cudaFuncAttributeMaxDynamicSharedMemorySize,
                         SMEM_BYTES);

    meganet<<<NCTA, NTHR, SMEM_BYTES>>>(batch_xs, batch_as, w_in, b_in,
                                        gcn_w, gcn_b, gidx, cp_mask, out);
}